// round 3
// baseline (speedup 1.0000x reference)
#include <cuda_runtime.h>
#include <stdint.h>

#define BATCH 128
#define N_RX 34
#define IMG_H 512
#define IMG_W 512
#define N_PIX (IMG_H * IMG_W)

// ---------------------------------------------------------------------------
// Kernel 1: zero the 256MB output with 16B vector stores (HBM-write bound,
// ~6.9 TB/s measured = at the roofline). Triggers PDL completion so the
// scatter kernel's prologue can overlap.
// ---------------------------------------------------------------------------
__global__ void zero_kernel(float4* __restrict__ out, int n4) {
    int i = blockIdx.x * blockDim.x + threadIdx.x;
    if (i < n4) {
        out[i] = make_float4(0.f, 0.f, 0.f, 0.f);
    }
    cudaTriggerProgrammaticLaunchCompletion();
}

// ---------------------------------------------------------------------------
// Kernel 2 (PDL secondary): one thread per batch. Prologue: load the batch's
// 34 points + weights, compute p/raw/offsets into registers (overlaps with
// zero_kernel). Then grid-dependency sync, then 68 stores in rx order.
// Same-thread stores to the same address are program-ordered => exact
// last-wins duplicate semantics with zero dedup logic.
// ---------------------------------------------------------------------------
__global__ void __launch_bounds__(1)
scatter_kernel(const float* __restrict__ x_vecs,
               const float* __restrict__ dw,
               const float* __restrict__ db,
               const float* __restrict__ cw,
               const float* __restrict__ cb,
               float* __restrict__ out) {
    const int b = blockIdx.x;

    float p[N_RX];
    float raw[N_RX];
    int   off[N_RX];

    const float4* xv = reinterpret_cast<const float4*>(x_vecs) + (size_t)b * N_RX;

    #pragma unroll
    for (int r = 0; r < N_RX; r++) {
        float4 v = xv[r];
        float rp   = v.x;
        float mask = (rp != 0.0f) ? 1.0f : 0.0f;
        float pp   = rp * dw[r] + mask * db[r];
        int   cat  = (int)v.w;
        pp = pp * cw[cat] + mask * cb[cat];
        int xx = (int)rintf(v.y);   // col 1 -> x
        int yy = (int)rintf(v.z);   // col 2 -> y
        p[r]   = pp;
        raw[r] = rp;
        off[r] = yy * IMG_W + xx;
    }

    // Wait for zero_kernel's stores to be visible, then scatter.
    cudaGridDependencySynchronize();

    float* base = out + (size_t)b * 2 * N_PIX;
    #pragma unroll
    for (int r = 0; r < N_RX; r++) {
        base[off[r]]         = p[r];     // channel 0
        base[N_PIX + off[r]] = raw[r];   // channel 1
    }
}

// ---------------------------------------------------------------------------
extern "C" void kernel_launch(void* const* d_in, const int* in_sizes, int n_in,
                              void* d_out, int out_size) {
    const float* x_vecs = (const float*)d_in[0];
    const float* dw     = (const float*)d_in[1];
    const float* db     = (const float*)d_in[2];
    const float* cw     = (const float*)d_in[3];
    const float* cb     = (const float*)d_in[4];
    float* out = (float*)d_out;

    int n4 = out_size / 4;   // 16,777,216 float4
    zero_kernel<<<(n4 + 255) / 256, 256>>>(reinterpret_cast<float4*>(out), n4);

    // PDL launch: scatter prologue overlaps with zero_kernel execution.
    cudaLaunchConfig_t cfg = {};
    cfg.gridDim  = dim3(BATCH, 1, 1);
    cfg.blockDim = dim3(1, 1, 1);
    cfg.dynamicSmemBytes = 0;
    cfg.stream = 0;
    cudaLaunchAttribute attr[1];
    attr[0].id = cudaLaunchAttributeProgrammaticStreamSerialization;
    attr[0].val.programmaticStreamSerializationAllowed = 1;
    cfg.attrs = attr;
    cfg.numAttrs = 1;
    cudaLaunchKernelEx(&cfg, scatter_kernel, x_vecs, dw, db, cw, cb, out);
}

// round 4
// speedup vs baseline: 1.7377x; 1.7377x over previous
#include <cuda_runtime.h>
#include <stdint.h>

#define BATCH 128
#define N_RX 34
#define IMG_H 512
#define IMG_W 512
#define N_PIX (IMG_H * IMG_W)

// ---------------------------------------------------------------------------
// Kernel 1: zero the 256MB output with 16B vector stores.
// Measured ~6.9 TB/s (~86% of HBM spec, at the LTS cap) — at the roofline.
// ---------------------------------------------------------------------------
__global__ void zero_kernel(float4* __restrict__ out, int n4) {
    int i = blockIdx.x * blockDim.x + threadIdx.x;
    if (i < n4) {
        out[i] = make_float4(0.f, 0.f, 0.f, 0.f);
    }
}

// ---------------------------------------------------------------------------
// Kernel 2: scatter. One 64-thread block per batch; threads 0..33 each own
// one point. Single parallel gmem load wave, smem-based last-wins dedup
// (a later rx hitting the same pixel suppresses this thread's write).
// ---------------------------------------------------------------------------
__global__ void __launch_bounds__(64)
scatter_kernel(const float* __restrict__ x_vecs,
               const float* __restrict__ dw,
               const float* __restrict__ db,
               const float* __restrict__ cw,
               const float* __restrict__ cb,
               float* __restrict__ out) {
    __shared__ int s_off[N_RX];

    const int b = blockIdx.x;
    const int r = threadIdx.x;

    float p = 0.f, raw = 0.f;
    int off = 0;

    if (r < N_RX) {
        const float4 v = *reinterpret_cast<const float4*>(
            x_vecs + ((size_t)b * N_RX + r) * 4);
        raw = v.x;
        float mask = (raw != 0.0f) ? 1.0f : 0.0f;
        p = raw * dw[r] + mask * db[r];
        int cat = (int)v.w;
        p = p * cw[cat] + mask * cb[cat];
        int xx = (int)rintf(v.y);   // col 1 -> x
        int yy = (int)rintf(v.z);   // col 2 -> y
        off = yy * IMG_W + xx;
        s_off[r] = off;
    }
    __syncthreads();

    if (r < N_RX) {
        // Last-wins: suppress if any LATER rx in this batch hits same pixel.
        bool write = true;
        #pragma unroll
        for (int rr = 0; rr < N_RX; rr++) {
            if (rr > r && s_off[rr] == off) write = false;
        }
        if (write) {
            float* base = out + (size_t)b * 2 * N_PIX;
            base[off]         = p;     // channel 0
            base[N_PIX + off] = raw;   // channel 1
        }
    }
}

// ---------------------------------------------------------------------------
extern "C" void kernel_launch(void* const* d_in, const int* in_sizes, int n_in,
                              void* d_out, int out_size) {
    const float* x_vecs = (const float*)d_in[0];
    const float* dw     = (const float*)d_in[1];
    const float* db     = (const float*)d_in[2];
    const float* cw     = (const float*)d_in[3];
    const float* cb     = (const float*)d_in[4];
    float* out = (float*)d_out;

    int n4 = out_size / 4;   // 16,777,216 float4
    zero_kernel<<<(n4 + 255) / 256, 256>>>(reinterpret_cast<float4*>(out), n4);

    scatter_kernel<<<BATCH, 64>>>(x_vecs, dw, db, cw, cb, out);
}